// round 17
// baseline (speedup 1.0000x reference)
#include <cuda_runtime.h>
#include <cuda_bf16.h>
#include <cstdint>

#define NPG 524288           // elements per (b, group)
#define NTOT 33554432        // B*C*H*W

// ---------------- device scratch (static allocation only) ----------------
static __device__ float     d_part[1024 * 2];      // GN partials
static __device__ uint32_t  d_wpack[8 * 128 * 64]; // [b][m][word]: wd<32 Whi pairs, wd>=32 Wlo pairs; m=2c+gu
static __device__ float     d_biaseff[8 * 128];    // [b][m], m=2c+gu
static __device__ float     d_gate[NTOT];
static __device__ float     d_hw[NTOT];

// ---------------- helpers --------------------------------------------------
__device__ __forceinline__ float sigmoid_tanh(float z) {
    float t;
    asm("tanh.approx.f32 %0, %1;" : "=f"(t) : "f"(z * 0.5f));
    return fmaf(0.5f, t, 0.5f);
}
__device__ __forceinline__ void bfsplit(float v, uint32_t& h, uint32_t& l) {
    __nv_bfloat16 hb = __float2bfloat16(v);
    float hf = __bfloat162float(hb);
    __nv_bfloat16 lb = __float2bfloat16(v - hf);
    h = (uint32_t)__bfloat16_as_ushort(hb);
    l = (uint32_t)__bfloat16_as_ushort(lb);
}
// m16n8k16 row.col f32.bf16.bf16.f32, D==C accumulate in place
__device__ __forceinline__ void mma_bf16(float* d, const uint32_t* a,
                                         uint32_t b0, uint32_t b1) {
    asm volatile(
        "mma.sync.aligned.m16n8k16.row.col.f32.bf16.bf16.f32 "
        "{%0,%1,%2,%3}, {%4,%5,%6,%7}, {%8,%9}, {%0,%1,%2,%3};"
        : "+f"(d[0]), "+f"(d[1]), "+f"(d[2]), "+f"(d[3])
        : "r"(a[0]), "r"(a[1]), "r"(a[2]), "r"(a[3]), "r"(b0), "r"(b1));
}

// ---------------- K1: GN partial stats (atomic-free) ---------------------
__global__ __launch_bounds__(256) void k_gn_stats(const float* __restrict__ x) {
    const int grp   = blockIdx.x >> 4;
    const int slice = blockIdx.x & 15;
    const float4* p = (const float4*)x + (size_t)grp * 131072 + slice * 8192;
    float s = 0.f, ss = 0.f;
#pragma unroll 4
    for (int i = threadIdx.x; i < 8192; i += 256) {
        float4 v = p[i];
        s  += (v.x + v.y) + (v.z + v.w);
        ss += (v.x * v.x + v.y * v.y) + (v.z * v.z + v.w * v.w);
    }
    for (int off = 16; off; off >>= 1) {
        s  += __shfl_down_sync(0xffffffffu, s,  off);
        ss += __shfl_down_sync(0xffffffffu, ss, off);
    }
    __shared__ float rs[8], rss[8];
    int w = threadIdx.x >> 5, l = threadIdx.x & 31;
    if (l == 0) { rs[w] = s; rss[w] = ss; }
    __syncthreads();
    if (threadIdx.x == 0) {
        float S = 0.f, SS = 0.f;
#pragma unroll
        for (int i = 0; i < 8; i++) { S += rs[i]; SS += rss[i]; }
        d_part[blockIdx.x * 2 + 0] = S;
        d_part[blockIdx.x * 2 + 1] = SS;
    }
}

// ---------------- K2: finalize stats + packed bf16-split weights ---------
__global__ __launch_bounds__(256) void k_weff(const float* __restrict__ gw,
                                              const float* __restrict__ gb,
                                              const float* __restrict__ uw,
                                              const float* __restrict__ ub,
                                              const float* __restrict__ gnw,
                                              const float* __restrict__ gnb) {
    const int b = blockIdx.x >> 3;
    const int slice = blockIdx.x & 7;
    __shared__ float smu[8], srstd[8];
    if (threadIdx.x < 8) {
        int g = b * 8 + threadIdx.x;
        double S = 0.0, SS = 0.0;
#pragma unroll
        for (int i = 0; i < 16; i++) {
            S  += (double)d_part[(g * 16 + i) * 2 + 0];
            SS += (double)d_part[(g * 16 + i) * 2 + 1];
        }
        const double n = (double)NPG;
        double mu  = S / n;
        double var = SS / n - mu * mu;
        smu[threadIdx.x]   = (float)mu;
        srstd[threadIdx.x] = (float)(1.0 / sqrt(var + 1e-5));
    }
    __syncthreads();
    const int base = slice * 1024;
#pragma unroll 4
    for (int i = 0; i < 4; i++) {
        int idx = base + i * 256 + threadIdx.x;   // 0..8191 per batch
        int m = idx >> 6, wd = idx & 63;
        int c = m >> 1, gu = m & 1;
        int k0 = (wd & 31) * 2;
        float w0 = gu ? uw[c * 64 + k0]     : gw[c * 64 + k0];
        float w1 = gu ? uw[c * 64 + k0 + 1] : gw[c * 64 + k0 + 1];
        float we0 = w0 * gnw[k0]     * srstd[k0 >> 3];
        float we1 = w1 * gnw[k0 + 1] * srstd[(k0 + 1) >> 3];
        uint32_t h0, l0, h1, l1;
        bfsplit(we0, h0, l0);
        bfsplit(we1, h1, l1);
        uint32_t word = (wd >= 32) ? (l0 | (l1 << 16)) : (h0 | (h1 << 16));
        d_wpack[b * 8192 + m * 64 + wd] = word;
    }
    if (slice == 0 && threadIdx.x < 128) {
        int o = threadIdx.x;
        int c = o & 63, gu = o >> 6;
        float acc = gu ? ub[c] : gb[c];
#pragma unroll 8
        for (int k = 0; k < 64; k++) {
            float w = gu ? uw[c * 64 + k] : gw[c * 64 + k];
            int g = k >> 3;
            acc += w * (gnb[k] - smu[g] * srstd[g] * gnw[k]);
        }
        d_biaseff[b * 128 + 2 * c + gu] = acc;
    }
}

// ---------------- dummy: keeps colmma in profiled launch slot #4 ---------
__global__ void k_nop() {}

// ---------------- K3: bf16-split mma.sync matvec + column scan -----------
// Grid 2048 = 8 b x 256 h, 256 threads (8 warps), 2 CTAs/SM, ~69KB dyn smem.
// Warp w: m-quarter mq = w>>1 (32 outputs, 2 m16 tiles), n-half nh = w&1
// (32 px, 4 n8 tiles). K=192: [Whi|Wlo|Whi] x [Xhi|Xhi|Xlo] (3-term split).
// lsm stride 68 (multiple of 4 -> float4-aligned odd rows; R15/16 bug was 66).
__global__ __launch_bounds__(256, 2) void k_colmma(const float* __restrict__ x) {
    extern __shared__ float sm[];
    uint32_t* Xhi = (uint32_t*)sm;        // [64 n][33 words] bf16 ch-pairs
    uint32_t* Xlo = Xhi + 2112;           // [64][33]
    uint32_t* Wls = Xhi + 4224;           // [128 m][33 words] Wlo (32 used)
    float*    lsm = sm + 8448;            // [128 m][68] logits (stride mult of 4)

    const int t    = threadIdx.x;
    const int b    = blockIdx.x >> 8;
    const int h    = blockIdx.x & 255;
    const int lane = t & 31, w = t >> 5;
    const int r = lane >> 2, cq = lane & 3;
    const int mq = w >> 1, nh = w & 1;
    const unsigned FULL = 0xffffffffu;

    const uint32_t* wb32 = d_wpack + b * 8192;   // row stride 64 words

    // Wlo -> smem (4096 words)
#pragma unroll
    for (int i = 0; i < 16; i++) {
        int idx = t + i * 256;
        int m = idx >> 5, k2 = idx & 31;
        Wls[m * 33 + k2] = wb32[m * 64 + 32 + k2];
    }

    // Ahi fragments resident: [mtile][kblock][4]
    uint32_t Ah[2][4][4];
#pragma unroll
    for (int mt = 0; mt < 2; mt++) {
        int m0 = mq * 32 + mt * 16 + r;
#pragma unroll
        for (int kb = 0; kb < 4; kb++) {
            int k2 = kb * 8 + cq;
            Ah[mt][kb][0] = wb32[m0 * 64 + k2];
            Ah[mt][kb][1] = wb32[(m0 + 8) * 64 + k2];
            Ah[mt][kb][2] = wb32[m0 * 64 + k2 + 4];
            Ah[mt][kb][3] = wb32[(m0 + 8) * 64 + k2 + 4];
        }
    }
    float bw[2][2];
#pragma unroll
    for (int mt = 0; mt < 2; mt++) {
        bw[mt][0] = d_biaseff[b * 128 + mq * 32 + mt * 16 + r];
        bw[mt][1] = d_biaseff[b * 128 + mq * 32 + mt * 16 + r + 8];
    }

    // scan ids (proven R10 epilogue shape)
    const int c = t >> 2, q = t & 3;
    float s_prev = 0.f;

    // x loader: f = px float4, cb = channel block of 4
    const int f = t & 15, cb = t >> 4;
    const float* xb = x + (size_t)b * 64 * 65536 + (size_t)h * 256;
    const float* gp[4];
#pragma unroll
    for (int j = 0; j < 4; j++)
        gp[j] = xb + (size_t)(cb * 4 + j) * 65536 + f * 4;
    float4 vin[4];
#pragma unroll
    for (int j = 0; j < 4; j++) vin[j] = *(const float4*)gp[j];

    __syncthreads();   // Wls visible

#pragma unroll 1
    for (int chk = 0; chk < 4; chk++) {
        // ---- stage X chunk (bf16 hi/lo, transposed [px][ch-pair]) ----
#pragma unroll
        for (int q3 = 0; q3 < 4; q3++) {
            int n = f * 4 + q3;
            float e0 = (q3 == 0) ? vin[0].x : (q3 == 1) ? vin[0].y : (q3 == 2) ? vin[0].z : vin[0].w;
            float e1 = (q3 == 0) ? vin[1].x : (q3 == 1) ? vin[1].y : (q3 == 2) ? vin[1].z : vin[1].w;
            float e2 = (q3 == 0) ? vin[2].x : (q3 == 1) ? vin[2].y : (q3 == 2) ? vin[2].z : vin[2].w;
            float e3 = (q3 == 0) ? vin[3].x : (q3 == 1) ? vin[3].y : (q3 == 2) ? vin[3].z : vin[3].w;
            uint32_t h0, l0, h1, l1, h2, l2, h3, l3;
            bfsplit(e0, h0, l0); bfsplit(e1, h1, l1);
            bfsplit(e2, h2, l2); bfsplit(e3, h3, l3);
            Xhi[n * 33 + 2 * cb]     = h0 | (h1 << 16);
            Xhi[n * 33 + 2 * cb + 1] = h2 | (h3 << 16);
            Xlo[n * 33 + 2 * cb]     = l0 | (l1 << 16);
            Xlo[n * 33 + 2 * cb + 1] = l2 | (l3 << 16);
        }
        __syncthreads();
        if (chk < 3) {
#pragma unroll
            for (int j = 0; j < 4; j++)
                vin[j] = *(const float4*)(gp[j] + (chk + 1) * 64);
        }

        // ---- MMA: 2 mtiles x 4 ntiles, 12 k-steps ----
        float acc[2][4][4];
#pragma unroll
        for (int mt = 0; mt < 2; mt++)
#pragma unroll
            for (int nt = 0; nt < 4; nt++) {
                acc[mt][nt][0] = bw[mt][0]; acc[mt][nt][1] = bw[mt][0];
                acc[mt][nt][2] = bw[mt][1]; acc[mt][nt][3] = bw[mt][1];
            }
#pragma unroll
        for (int s = 0; s < 12; s++) {
            const int kb = s & 3;
            const uint32_t* Xarr = (s < 8) ? Xhi : Xlo;
            uint32_t Af0[4], Af1[4];
            if (s >= 4 && s < 8) {
                int kl = kb * 8 + cq;
                int m0 = mq * 32 + r, m1 = m0 + 16;
                Af0[0] = Wls[m0 * 33 + kl];       Af0[1] = Wls[(m0 + 8) * 33 + kl];
                Af0[2] = Wls[m0 * 33 + kl + 4];   Af0[3] = Wls[(m0 + 8) * 33 + kl + 4];
                Af1[0] = Wls[m1 * 33 + kl];       Af1[1] = Wls[(m1 + 8) * 33 + kl];
                Af1[2] = Wls[m1 * 33 + kl + 4];   Af1[3] = Wls[(m1 + 8) * 33 + kl + 4];
            } else {
#pragma unroll
                for (int p = 0; p < 4; p++) { Af0[p] = Ah[0][kb][p]; Af1[p] = Ah[1][kb][p]; }
            }
#pragma unroll
            for (int nt = 0; nt < 4; nt++) {
                int n = nh * 32 + nt * 8 + r;
                uint32_t b0 = Xarr[n * 33 + kb * 8 + cq];
                uint32_t b1 = Xarr[n * 33 + kb * 8 + 4 + cq];
                mma_bf16(acc[0][nt], Af0, b0, b1);
                mma_bf16(acc[1][nt], Af1, b0, b1);
            }
        }
        // ---- D -> lsm (stride 68) ----
#pragma unroll
        for (int mt = 0; mt < 2; mt++)
#pragma unroll
            for (int nt = 0; nt < 4; nt++) {
                int m0 = mq * 32 + mt * 16 + r;
                int n0 = nh * 32 + nt * 8 + 2 * cq;
                *(float2*)&lsm[m0 * 68 + n0] =
                    make_float2(acc[mt][nt][0], acc[mt][nt][1]);
                *(float2*)&lsm[(m0 + 8) * 68 + n0] =
                    make_float2(acc[mt][nt][2], acc[mt][nt][3]);
            }
        __syncthreads();

        // ---- scan: thread owns channel c, px quarter q (16 px) ----
        float gv[16], uv[16];
        {
            const float* lg = &lsm[(2 * c) * 68 + q * 16];
            const float* lu = &lsm[(2 * c + 1) * 68 + q * 16];
#pragma unroll
            for (int j4 = 0; j4 < 4; j4++) {
                float4 a = *(const float4*)(lg + j4 * 4);
                float4 d = *(const float4*)(lu + j4 * 4);
                gv[j4*4+0] = a.x; gv[j4*4+1] = a.y; gv[j4*4+2] = a.z; gv[j4*4+3] = a.w;
                uv[j4*4+0] = d.x; uv[j4*4+1] = d.y; uv[j4*4+2] = d.z; uv[j4*4+3] = d.w;
            }
        }
#pragma unroll
        for (int j = 0; j < 16; j++) {
            gv[j] = sigmoid_tanh(gv[j]);
            uv[j] = fmaf(-gv[j], uv[j], uv[j]);   // (1-g)*u
        }
        float Ac = 1.f, Bc = 0.f;
#pragma unroll
        for (int j = 0; j < 16; j++) {
            Ac = Ac * gv[j];
            Bc = fmaf(gv[j], Bc, uv[j]);
        }
        // width-4 inclusive Hillis-Steele over q lanes
        float Ai = Ac, Bi = Bc;
        {
            float Au = __shfl_up_sync(FULL, Ai, 1, 4);
            float Bu = __shfl_up_sync(FULL, Bi, 1, 4);
            if (q >= 1) { Bi = fmaf(Ai, Bu, Bi); Ai *= Au; }
            Au = __shfl_up_sync(FULL, Ai, 2, 4);
            Bu = __shfl_up_sync(FULL, Bi, 2, 4);
            if (q >= 2) { Bi = fmaf(Ai, Bu, Bi); Ai *= Au; }
        }
        float Ax = __shfl_up_sync(FULL, Ai, 1, 4);
        float Bx = __shfl_up_sync(FULL, Bi, 1, 4);
        float sin0 = (q == 0) ? s_prev : fmaf(Ax, s_prev, Bx);
        float A3 = __shfl_sync(FULL, Ai, 3, 4);
        float B3 = __shfl_sync(FULL, Bi, 3, 4);
        s_prev = fmaf(A3, s_prev, B3);

        // sequential re-apply + writeback
        int gi = (((b * 64 + c) * 256 + h) * 256) + chk * 64 + q * 16;
        float s = sin0;
#pragma unroll
        for (int j4 = 0; j4 < 4; j4++) {
            float4 sv;
            s = fmaf(gv[j4*4+0], s, uv[j4*4+0]); sv.x = s;
            s = fmaf(gv[j4*4+1], s, uv[j4*4+1]); sv.y = s;
            s = fmaf(gv[j4*4+2], s, uv[j4*4+2]); sv.z = s;
            s = fmaf(gv[j4*4+3], s, uv[j4*4+3]); sv.w = s;
            *(float4*)(d_gate + gi + j4 * 4) =
                make_float4(gv[j4*4], gv[j4*4+1], gv[j4*4+2], gv[j4*4+3]);
            *(float4*)(d_hw + gi + j4 * 4) = sv;
        }
        __syncthreads();   // lsm free; X safe to restage next iter
    }
}

// ---------------- K4: row scan over H + residual add ---------------------
__global__ __launch_bounds__(128) void k_rowscan(const float* __restrict__ x,
                                                 float* __restrict__ out) {
    const int idx  = blockIdx.x * 128 + threadIdx.x;     // 0..131071
    const int base = (idx >> 8) * 65536 + (idx & 255);   // (b*64+c)*HW + w
    float s = 0.f;
#pragma unroll 1
    for (int h = 0; h < 256; h += 8) {
        const int r = base + (h << 8);
        float g[8], u[8], xv[8];
#pragma unroll
        for (int j = 0; j < 8; j++) g[j] = d_gate[r + (j << 8)];
#pragma unroll
        for (int j = 0; j < 8; j++) u[j] = d_hw[r + (j << 8)];
#pragma unroll
        for (int j = 0; j < 8; j++) xv[j] = __ldcs(&x[r + (j << 8)]);
#pragma unroll
        for (int j = 0; j < 8; j++) {
            s = fmaf(g[j], s, fmaf(-g[j], u[j], u[j]));
            __stcs(&out[r + (j << 8)], xv[j] + s);
        }
    }
}

// ---------------- launch --------------------------------------------------
#define COLMMA_SMEM (17152 * 4)   // 68,608 bytes (Xhi/Xlo/Wls + lsm stride 68)

extern "C" void kernel_launch(void* const* d_in, const int* in_sizes, int n_in,
                              void* d_out, int out_size) {
    const float* x      = (const float*)d_in[0];
    const float* gn_w   = (const float*)d_in[1];
    const float* gn_b   = (const float*)d_in[2];
    const float* gate_w = (const float*)d_in[3];
    const float* gate_b = (const float*)d_in[4];
    const float* upd_w  = (const float*)d_in[5];
    const float* upd_b  = (const float*)d_in[6];
    float* out = (float*)d_out;

    cudaFuncSetAttribute(k_colmma,
                         cudaFuncAttributeMaxDynamicSharedMemorySize,
                         COLMMA_SMEM);

    k_gn_stats<<<1024, 256>>>(x);
    k_weff<<<64, 256>>>(gate_w, gate_b, upd_w, upd_b, gn_w, gn_b);
    k_nop<<<1, 32>>>();                 // keeps k_colmma in profiled slot
    k_colmma<<<2048, 256, COLMMA_SMEM>>>(x);
    k_rowscan<<<1024, 128>>>(x, out);
}